// round 9
// baseline (speedup 1.0000x reference)
#include <cuda_runtime.h>

#define FULL 0xFFFFFFFFu
static const int NROW = 25200;
static const int BIMG = 8;
static const int NBIN = 2048;
static const int KC   = 512;
static const int KP   = 1024;
static const int TILE = 112;               // 25200 = 225 * 112
static const int NTILE = NROW / TILE;      // 225

// ---------------- global scratch (static __device__, no allocation) -------
__device__ __align__(16) unsigned long long g_keys[2][BIMG][NROW];
__device__ int            g_hist[16][NBIN];
__device__ float4         g_box [2][BIMG][KP];
__device__ unsigned char  g_cls [2][BIMG][KP];
__device__ unsigned char  g_keep[2][BIMG][KP];
__device__ int            g_flag[BIMG];    // patch segment done flags
__device__ float          g_s[BIMG], g_n[BIMG];
__device__ int            g_cnt;

__device__ __forceinline__ float iou_rn(float4 a, float4 b) {
    float tlx = fmaxf(a.x, b.x), tly = fmaxf(a.y, b.y);
    float brx = fminf(a.z, b.z), bry = fminf(a.w, b.w);
    float w = fmaxf(__fsub_rn(brx, tlx), 0.0f);
    float h = fmaxf(__fsub_rn(bry, tly), 0.0f);
    float inter = __fmul_rn(w, h);
    float aa = __fmul_rn(__fsub_rn(a.z, a.x), __fsub_rn(a.w, a.y));
    float ab = __fmul_rn(__fsub_rn(b.z, b.x), __fsub_rn(b.w, b.y));
    float uni = __fsub_rn(__fadd_rn(aa, ab), inter);
    uni = (uni > 0.0f) ? uni : 1.0f;
    return __fdiv_rn(inter, uni);
}

__device__ __forceinline__ int binof(float conf) {
    int b = (int)(__fmul_rn(conf, 2048.0f));
    return b > NBIN - 1 ? NBIN - 1 : (b < 0 ? 0 : b);
}

// biased high-word of the smallest positive float whose bin >= B (exact).
__device__ __forceinline__ unsigned cut_for(int B) {
    if (B <= 0) return 0x80000001u;
    if (B > NBIN - 1) return 0xFFFFFFFFu;
    float g = (float)B / 2048.0f;
    for (;;) {
        float p = __int_as_float(__float_as_int(g) - 1);
        if ((int)(__fmul_rn(p, 2048.0f)) >= B) g = p; else break;
    }
    return __float_as_uint(g) ^ 0x80000000u;
}

__device__ __forceinline__ int redux_max_s32(int v) {
    int r; asm volatile("redux.sync.max.s32 %0, %1, 0xffffffff;" : "=r"(r) : "r"(v)); return r;
}
__device__ __forceinline__ int redux_min_s32(int v) {
    int r; asm volatile("redux.sync.min.s32 %0, %1, 0xffffffff;" : "=r"(r) : "r"(v)); return r;
}

// ---------------- K1: tile-staged score / key / histogram ------------------
// grid (225, 16), block 128. Raw class max (no index): RN-mult by obj>0 is
// monotone, so max_c RN(cls*obj) == RN(max_c cls * obj) bit-exactly.
__global__ void __launch_bounds__(128) k_score(const float* __restrict__ clean,
                                               const float* __restrict__ patch) {
    __shared__ float sd[TILE * 85];
    int seg   = blockIdx.y;
    int which = seg >> 3, img = seg & 7;
    int tile  = blockIdx.x;
    const float* base = (which ? patch : clean)
                      + ((size_t)img * NROW + (size_t)tile * TILE) * 85;
    const float4* b4 = (const float4*)base;
    float4* s4 = (float4*)sd;
    const int NV4 = TILE * 85 / 4;                      // 2380
    #pragma unroll 5
    for (int i = threadIdx.x; i < NV4; i += 128) s4[i] = b4[i];
    __syncthreads();

    int tid = threadIdx.x;
    if (tid < TILE) {
        const float* row = sd + tid * 85;
        float obj = row[4];
        float m0 = row[5], m1 = row[6], m2 = row[7], m3 = row[8];
        #pragma unroll
        for (int c = 9; c < 85; c += 4) {
            m0 = fmaxf(m0, row[c]);     m1 = fmaxf(m1, row[c + 1]);
            m2 = fmaxf(m2, row[c + 2]); m3 = fmaxf(m3, row[c + 3]);
        }
        float conf = __fmul_rn(fmaxf(fmaxf(m0, m1), fmaxf(m2, m3)), obj);
        int r = tile * TILE + tid;
        float TH = which ? 0.001f : 0.25f;
        unsigned long long key = 0ull;
        if (obj > TH && conf > TH) {
            unsigned u = __float_as_uint(conf) ^ 0x80000000u;
            key = ((unsigned long long)u << 32) | ((unsigned)(32767 - r) << 7);
            atomicAdd(&g_hist[seg][binof(conf)], 1);
        }
        g_keys[which][img][r] = key;                    // coalesced
    }
}

// ---------------- K2: threshold + gather + tie + NMS + fused loss ----------
__global__ void __launch_bounds__(1024) k_select(const float* __restrict__ clean,
                                                 const float* __restrict__ patch,
                                                 float* __restrict__ out) {
    __shared__ union {
        struct {
            unsigned long long skey[KP];
            unsigned long long tie[512];
            float4 obox[KP];
            short  clslist[80 * 64];
        } sel;
        struct {
            float4 pdiv[KP];
            short  plist[80 * 128];
        } loss;
    } U;
    __shared__ unsigned char keepc[KP];
    __shared__ int   ccnt[80];
    __shared__ int   wsum[32];
    __shared__ float rs[32], rn2[32];
    __shared__ int   sT, sNeed, sAllin, sNin, sNtie;
    __shared__ unsigned sCutIn, sCutTie;

    int seg = blockIdx.x;
    int which = seg >> 3, img = seg & 7;
    int K = which ? KP : KC;
    const float* src = (which ? patch : clean) + (size_t)img * NROW * 85;
    const unsigned long long* keys = g_keys[which][img];
    int tid = threadIdx.x, lane = tid & 31, w = tid >> 5;

    // --- Phase A: threshold from histogram (descending-bin chunks) ---
    const int CH = NBIN / 1024;                  // 2
    int hi = NBIN - CH * tid, lo = hi - CH;
    int s = g_hist[seg][lo] + g_hist[seg][lo + 1];
    int inc = s;
    #pragma unroll
    for (int off = 1; off < 32; off <<= 1) {
        int n = __shfl_up_sync(FULL, inc, off);
        if (lane >= off) inc += n;
    }
    if (lane == 31) wsum[w] = inc;
    if (tid == 0) { sNin = 0; sNtie = 0; sT = 0; sNeed = 0; }
    if (tid < 80) ccnt[tid] = 0;
    __syncthreads();
    if (w == 0) {
        int v = wsum[lane];
        #pragma unroll
        for (int off = 1; off < 32; off <<= 1) {
            int n = __shfl_up_sync(FULL, v, off);
            if (lane >= off) v += n;
        }
        wsum[lane] = v;
    }
    __syncthreads();
    int wbase = w ? wsum[w - 1] : 0;
    int incl = wbase + inc, excl = incl - s;
    int total = wsum[31];
    if (tid == 0) sAllin = (total <= K);
    if (total > K && excl < K && incl >= K) {     // unique crossing thread
        int acc = excl, tb = lo, hv = 0;
        for (int b = hi - 1; b >= lo; b--) {
            hv = g_hist[seg][b]; acc += hv;
            if (acc >= K) { tb = b; break; }
        }
        sT = tb;
        sNeed = K - (acc - hv);
    }
    __syncthreads();
    int T = sT, allin = sAllin, need = sNeed;
    if (tid == 0) {
        if (allin) { sCutIn = 0x80000001u; sCutTie = 0x80000001u; }
        else       { sCutIn = cut_for(T + 1); sCutTie = cut_for(T); }
    }
    for (int i = tid; i < NBIN; i += 1024) g_hist[seg][i] = 0;   // next replay
    __syncthreads();
    unsigned cutIn = sCutIn, cutTie = sCutTie;
    if (allin) cutTie = cutIn;                    // tie set empty

    // --- Phase B: vectorized gather, 4 keys/thread/iter ---
    const ulonglong2* keys2 = (const ulonglong2*)keys;
    const int NP = NROW / 2;                      // 12600
    const unsigned lmlt = (1u << lane) - 1u;
    for (int it = 0; it < 7; it++) {
        int i0 = it * 2048 + tid, i1 = i0 + 1024;
        ulonglong2 ka, kb;
        if (i0 < NP) ka = keys2[i0]; else { ka.x = 0; ka.y = 0; }
        if (i1 < NP) kb = keys2[i1]; else { kb.x = 0; kb.y = 0; }
        unsigned h0 = (unsigned)(ka.x >> 32), h1 = (unsigned)(ka.y >> 32);
        unsigned h2 = (unsigned)(kb.x >> 32), h3 = (unsigned)(kb.y >> 32);
        bool in0 = h0 >= cutIn, in1 = h1 >= cutIn, in2 = h2 >= cutIn, in3 = h3 >= cutIn;
        unsigned m0 = __ballot_sync(FULL, in0), m1 = __ballot_sync(FULL, in1);
        unsigned m2 = __ballot_sync(FULL, in2), m3 = __ballot_sync(FULL, in3);
        int tot = __popc(m0) + __popc(m1) + __popc(m2) + __popc(m3);
        if (tot) {
            int leader = __ffs(m0 | m1 | m2 | m3) - 1, base = 0;
            if (lane == leader) base = atomicAdd(&sNin, tot);
            base = __shfl_sync(FULL, base, leader);
            int c0 = __popc(m0), c1 = __popc(m1), c2p = __popc(m2);
            if (in0) U.sel.skey[base + __popc(m0 & lmlt)] = ka.x;
            if (in1) U.sel.skey[base + c0 + __popc(m1 & lmlt)] = ka.y;
            if (in2) U.sel.skey[base + c0 + c1 + __popc(m2 & lmlt)] = kb.x;
            if (in3) U.sel.skey[base + c0 + c1 + c2p + __popc(m3 & lmlt)] = kb.y;
        }
        if (!in0 && h0 >= cutTie) { int p = atomicAdd(&sNtie, 1); if (p < 512) U.sel.tie[p] = ka.x; }
        if (!in1 && h1 >= cutTie) { int p = atomicAdd(&sNtie, 1); if (p < 512) U.sel.tie[p] = ka.y; }
        if (!in2 && h2 >= cutTie) { int p = atomicAdd(&sNtie, 1); if (p < 512) U.sel.tie[p] = kb.x; }
        if (!in3 && h3 >= cutTie) { int p = atomicAdd(&sNtie, 1); if (p < 512) U.sel.tie[p] = kb.y; }
    }
    __syncthreads();
    int nin = sNin;
    int S;
    if (!allin && need > 0) {
        int nt = sNtie; if (nt > 512) nt = 512;
        int P = 2; while (P < nt) P <<= 1;
        for (int i = tid; i < P; i += 1024) if (i >= nt) U.sel.tie[i] = 0ull;
        __syncthreads();
        for (int k = 2; k <= P; k <<= 1)
            for (int j = k >> 1; j; j >>= 1) {
                for (int e = tid; e < P; e += 1024) {
                    int p = e ^ j;
                    if (p > e) {
                        unsigned long long a = U.sel.tie[e], b2 = U.sel.tie[p];
                        bool dsc = ((e & k) == 0);
                        if ((a < b2) == dsc) { U.sel.tie[e] = b2; U.sel.tie[p] = a; }
                    }
                }
                __syncthreads();
            }
        for (int t2 = tid; t2 < need; t2 += 1024) U.sel.skey[nin + t2] = U.sel.tie[t2];
        S = nin + need;
    } else {
        S = nin;
    }
    __syncthreads();

    // --- Phase C: warp-cooperative decode (exact earliest product-argmax) ---
    for (int slot = w; slot < S; slot += 32) {
        unsigned long long key = U.sel.skey[slot];
        int idx = 32767 - (int)((key >> 7) & 32767u);
        const float* rp = src + (size_t)idx * 85;
        float a  = rp[lane];
        float b  = rp[32 + lane];
        float c2 = (lane < 21) ? rp[64 + lane] : 0.0f;
        float obj = __shfl_sync(FULL, a, 4);
        int pai = (lane >= 5) ? __float_as_int(__fmul_rn(a, obj))  : (int)0x80000000;
        int pbi =               __float_as_int(__fmul_rn(b, obj));
        int pci = (lane < 21) ? __float_as_int(__fmul_rn(c2, obj)) : (int)0x80000000;
        int vm = redux_max_s32(max(pai, max(pbi, pci)));
        int ca = (pai == vm) ? lane      : 0x7FFFFFFF;
        int cb = (pbi == vm) ? lane + 32 : 0x7FFFFFFF;
        int cc = (pci == vm) ? lane + 64 : 0x7FFFFFFF;
        int col = redux_min_s32(min(ca, min(cb, cc)));
        int cls = col - 5;
        float cx = __shfl_sync(FULL, a, 0), cy = __shfl_sync(FULL, a, 1);
        float ww2 = __shfl_sync(FULL, a, 2), hh2 = __shfl_sync(FULL, a, 3);
        if (lane == 0) {
            float hw = __fmul_rn(ww2, 0.5f), hh = __fmul_rn(hh2, 0.5f);
            float4 pb4, ob;
            pb4.x = __fsub_rn(cx, hw); pb4.y = __fsub_rn(cy, hh);
            pb4.z = __fadd_rn(cx, hw); pb4.w = __fadd_rn(cy, hh);
            float off = (float)cls * 4096.0f;
            ob.x = __fadd_rn(pb4.x, off); ob.y = __fadd_rn(pb4.y, off);
            ob.z = __fadd_rn(pb4.z, off); ob.w = __fadd_rn(pb4.w, off);
            g_box[which][img][slot] = pb4;
            g_cls[which][img][slot] = (unsigned char)cls;
            U.sel.obox[slot] = ob;
            keepc[slot] = 1;
            int p = atomicAdd(&ccnt[cls], 1);
            if (p < 64) U.sel.clslist[cls * 64 + p] = (short)slot;
            else        g_keep[which][img][slot] = 1;   // overflow: treat as kept
        }
    }
    for (int i = S + tid; i < K; i += 1024) g_keep[which][img][i] = 0;
    __syncthreads();

    // --- Phase D: per-class NMS, one warp per class ---
    for (int c = w; c < 80; c += 32) {
        int m = ccnt[c]; if (m > 64) m = 64;
        int base2 = c * 64;
        if (m == 0) continue;
        if (m == 1) {
            if (lane == 0) { int id = U.sel.clslist[base2]; g_keep[which][img][id] = 1; }
            continue;
        }
        if (m <= 32) {
            int id = (lane < m) ? U.sel.clslist[base2 + lane] : -1;
            unsigned long long kk = (lane < m) ? U.sel.skey[id] : 0ull;
            unsigned hi32 = (unsigned)(kk >> 32), lo32 = (unsigned)kk;
            int rank = 0;
            for (int j = 0; j < m; j++) {
                unsigned hj = __shfl_sync(FULL, hi32, j);
                unsigned lj = __shfl_sync(FULL, lo32, j);
                if (hj > hi32 || (hj == hi32 && lj > lo32)) rank++;
            }
            if (lane < m) U.sel.clslist[base2 + rank] = (short)id;
            __syncwarp();
            id = (lane < m) ? U.sel.clslist[base2 + lane] : -1;
            float4 B = (lane < m) ? U.sel.obox[id] : make_float4(0.f, 0.f, 0.f, 0.f);
            unsigned keepb = (m >= 32) ? FULL : ((1u << m) - 1u);
            for (int a = 0; a < m - 1; a++) {
                if ((keepb >> a) & 1u) {
                    float4 A;
                    A.x = __shfl_sync(FULL, B.x, a);
                    A.y = __shfl_sync(FULL, B.y, a);
                    A.z = __shfl_sync(FULL, B.z, a);
                    A.w = __shfl_sync(FULL, B.w, a);
                    bool sup = (lane > a) && (lane < m) && ((keepb >> lane) & 1u)
                               && (iou_rn(A, B) > 0.45f);
                    keepb &= ~__ballot_sync(FULL, sup);
                }
            }
            if (lane < m) g_keep[which][img][id] = (unsigned char)((keepb >> lane) & 1u);
        } else {
            if (lane == 0) {
                for (int i2 = 1; i2 < m; i2++) {
                    short v = U.sel.clslist[base2 + i2];
                    unsigned long long kv = U.sel.skey[v];
                    int j2 = i2 - 1;
                    while (j2 >= 0 && U.sel.skey[U.sel.clslist[base2 + j2]] < kv) {
                        U.sel.clslist[base2 + j2 + 1] = U.sel.clslist[base2 + j2]; j2--;
                    }
                    U.sel.clslist[base2 + j2 + 1] = v;
                }
            }
            __syncwarp();
            for (int a = 0; a < m - 1; a++) {
                int ta = U.sel.clslist[base2 + a];
                if (keepc[ta]) {
                    float4 A = U.sel.obox[ta];
                    for (int b = a + 1 + lane; b < m; b += 32) {
                        int tb = U.sel.clslist[base2 + b];
                        if (keepc[tb] && iou_rn(A, U.sel.obox[tb]) > 0.45f) keepc[tb] = 0;
                    }
                }
                __syncwarp();
            }
            for (int b = lane; b < m; b += 32) {
                int tb = U.sel.clslist[base2 + b];
                g_keep[which][img][tb] = keepc[tb];
            }
        }
    }
    __syncthreads();

    // --- Phase E: handshake + fused loss ---
    if (which == 1) {                         // patch: publish and exit
        __threadfence();
        if (tid == 0) atomicExch(&g_flag[img], 1);
        return;
    }

    int myk = 0, myc2 = 0;
    float4 myb = make_float4(0.f, 0.f, 0.f, 0.f);
    if (tid < KC) {
        myk  = g_keep[0][img][tid];
        myc2 = g_cls [0][img][tid];
        myb  = g_box [0][img][tid];
    }
    if (tid == 0) { while (atomicAdd(&g_flag[img], 0) == 0) {} }
    __syncthreads();                          // flag seen -> patch data visible
    if (tid < 80) ccnt[tid] = 0;
    __syncthreads();

    {
        int pk = g_keep[1][img][tid];
        int pc = g_cls [1][img][tid];
        float4 pb = g_box[1][img][tid];
        U.loss.pdiv[tid] = make_float4(__fdiv_rn(pb.x, 640.0f), __fdiv_rn(pb.y, 640.0f),
                                       __fdiv_rn(pb.z, 640.0f), __fdiv_rn(pb.w, 640.0f));
        if (pk) {
            int p = atomicAdd(&ccnt[pc], 1);
            if (p < 128) U.loss.plist[pc * 128 + p] = (short)tid;
        }
    }
    __syncthreads();

    float ss = 0.0f, nn = 0.0f;
    if (tid < KC && myk) {
        nn = 1.0f;
        float4 cd = make_float4(__fdiv_rn(myb.x, 640.0f), __fdiv_rn(myb.y, 640.0f),
                                __fdiv_rn(myb.z, 640.0f), __fdiv_rn(myb.w, 640.0f));
        float tm = 0.0f;
        int m = ccnt[myc2]; if (m > 128) m = 128;
        int base2 = myc2 * 128;
        for (int b2 = 0; b2 < m; b2++)
            tm = fmaxf(tm, iou_rn(cd, U.loss.pdiv[U.loss.plist[base2 + b2]]));
        ss = tm;
    }
    #pragma unroll
    for (int off = 16; off; off >>= 1) {
        ss += __shfl_down_sync(FULL, ss, off);
        nn += __shfl_down_sync(FULL, nn, off);
    }
    if (lane == 0) { rs[w] = ss; rn2[w] = nn; }
    __syncthreads();
    if (tid == 0) {
        float Sm = 0.0f, Nm = 0.0f;
        #pragma unroll
        for (int i = 0; i < 32; i++) { Sm += rs[i]; Nm += rn2[i]; }
        g_s[img] = Sm; g_n[img] = Nm;
        __threadfence();
        int old = atomicAdd(&g_cnt, 1);
        if (old == BIMG - 1) {
            float tot = 0.0f, cnt = 0.0f;
            for (int i = 0; i < BIMG; i++) { tot += g_s[i]; cnt += g_n[i]; }
            out[0] = (cnt > 0.0f) ? __fsub_rn(1.0f, __fdiv_rn(tot, fmaxf(cnt, 1.0f)))
                                  : 1.0f;
            g_cnt = 0;
        }
        g_flag[img] = 0;                       // reset for next replay
    }
}

// ---------------- launch ----------------------------------------------------
extern "C" void kernel_launch(void* const* d_in, const int* in_sizes, int n_in,
                              void* d_out, int out_size) {
    const float* clean = (const float*)d_in[0];
    const float* patch = (const float*)d_in[1];

    dim3 sgrid(NTILE, 16);                     // 225 x 16 tiles
    k_score<<<sgrid, 128>>>(clean, patch);
    k_select<<<16, 1024>>>(clean, patch, (float*)d_out);
}

// round 10
// speedup vs baseline: 1.0466x; 1.0466x over previous
#include <cuda_runtime.h>

#define FULL 0xFFFFFFFFu
static const int NROW = 25200;
static const int BIMG = 8;
static const int NBIN = 2048;
static const int KC   = 512;
static const int KP   = 1024;
static const int TILE = 112;               // 25200 = 225 * 112
static const int NTILE = NROW / TILE;      // 225

// ---------------- global scratch (static __device__, no allocation) -------
__device__ __align__(16) unsigned long long g_keys[2][BIMG][NROW];
__device__ int            g_hist[16][NBIN];
__device__ float4         g_box [2][BIMG][KP];
__device__ unsigned char  g_cls [2][BIMG][KP];
__device__ unsigned char  g_keep[2][BIMG][KP];
__device__ int            g_flag[BIMG];    // patch segment done flags
__device__ float          g_s[BIMG], g_n[BIMG];
__device__ int            g_cnt;

__device__ __forceinline__ float iou_rn(float4 a, float4 b) {
    float tlx = fmaxf(a.x, b.x), tly = fmaxf(a.y, b.y);
    float brx = fminf(a.z, b.z), bry = fminf(a.w, b.w);
    float w = fmaxf(__fsub_rn(brx, tlx), 0.0f);
    float h = fmaxf(__fsub_rn(bry, tly), 0.0f);
    float inter = __fmul_rn(w, h);
    float aa = __fmul_rn(__fsub_rn(a.z, a.x), __fsub_rn(a.w, a.y));
    float ab = __fmul_rn(__fsub_rn(b.z, b.x), __fsub_rn(b.w, b.y));
    float uni = __fsub_rn(__fadd_rn(aa, ab), inter);
    uni = (uni > 0.0f) ? uni : 1.0f;
    return __fdiv_rn(inter, uni);
}

__device__ __forceinline__ int binof(float conf) {
    int b = (int)(__fmul_rn(conf, 2048.0f));
    return b > NBIN - 1 ? NBIN - 1 : (b < 0 ? 0 : b);
}

// biased high-word of the smallest positive float whose bin >= B (exact).
__device__ __forceinline__ unsigned cut_for(int B) {
    if (B <= 0) return 0x80000001u;
    if (B > NBIN - 1) return 0xFFFFFFFFu;
    float g = (float)B / 2048.0f;
    for (;;) {
        float p = __int_as_float(__float_as_int(g) - 1);
        if ((int)(__fmul_rn(p, 2048.0f)) >= B) g = p; else break;
    }
    return __float_as_uint(g) ^ 0x80000000u;
}

// ---------------- K1: tile-staged score / key / histogram ------------------
// Raw class max (no index): RN-mult by obj>0 is monotone, so
// max_c RN(cls*obj) == RN(max_c cls * obj) bit-exactly.
__global__ void __launch_bounds__(128) k_score(const float* __restrict__ clean,
                                               const float* __restrict__ patch) {
    __shared__ float sd[TILE * 85];
    int seg   = blockIdx.y;
    int which = seg >> 3, img = seg & 7;
    int tile  = blockIdx.x;
    const float* base = (which ? patch : clean)
                      + ((size_t)img * NROW + (size_t)tile * TILE) * 85;
    const float4* b4 = (const float4*)base;
    float4* s4 = (float4*)sd;
    const int NV4 = TILE * 85 / 4;                      // 2380
    #pragma unroll 5
    for (int i = threadIdx.x; i < NV4; i += 128) s4[i] = b4[i];
    __syncthreads();

    int tid = threadIdx.x;
    if (tid < TILE) {
        const float* row = sd + tid * 85;
        float obj = row[4];
        float m0 = row[5], m1 = row[6], m2 = row[7], m3 = row[8];
        #pragma unroll
        for (int c = 9; c < 85; c += 4) {
            m0 = fmaxf(m0, row[c]);     m1 = fmaxf(m1, row[c + 1]);
            m2 = fmaxf(m2, row[c + 2]); m3 = fmaxf(m3, row[c + 3]);
        }
        float conf = __fmul_rn(fmaxf(fmaxf(m0, m1), fmaxf(m2, m3)), obj);
        int r = tile * TILE + tid;
        float TH = which ? 0.001f : 0.25f;
        unsigned long long key = 0ull;
        if (obj > TH && conf > TH) {
            unsigned u = __float_as_uint(conf) ^ 0x80000000u;
            key = ((unsigned long long)u << 32) | ((unsigned)(32767 - r) << 7);
            atomicAdd(&g_hist[seg][binof(conf)], 1);
        }
        g_keys[which][img][r] = key;                    // coalesced
    }
}

// ---------------- K2: threshold + gather + tie + NMS + fused loss ----------
__global__ void __launch_bounds__(1024) k_select(const float* __restrict__ clean,
                                                 const float* __restrict__ patch,
                                                 float* __restrict__ out) {
    __shared__ union {
        struct {
            unsigned long long skey[KP];
            unsigned long long tie[1024];
            float4 obox[KP];
            short  clslist[80 * 64];
        } sel;
        struct {
            float4 pdiv[KP];
            short  plist[80 * 128];
        } loss;
    } U;
    __shared__ unsigned char keepc[KP];
    __shared__ int   ccnt[80];
    __shared__ int   wsum[32];
    __shared__ float rs[32], rn2[32];
    __shared__ int   sT, sNeed, sAllin, sNin, sNtie;
    __shared__ unsigned sCutIn, sCutTie;

    int seg = blockIdx.x;
    int which = seg >> 3, img = seg & 7;
    int K = which ? KP : KC;
    const float* src = (which ? patch : clean) + (size_t)img * NROW * 85;
    const unsigned long long* keys = g_keys[which][img];
    int tid = threadIdx.x, lane = tid & 31, w = tid >> 5;

    // --- Phase A: threshold from histogram (descending-bin chunks) ---
    const int CH = NBIN / 1024;                  // 2
    int hi = NBIN - CH * tid, lo = hi - CH;
    int s = g_hist[seg][lo] + g_hist[seg][lo + 1];
    int inc = s;
    #pragma unroll
    for (int off = 1; off < 32; off <<= 1) {
        int n = __shfl_up_sync(FULL, inc, off);
        if (lane >= off) inc += n;
    }
    if (lane == 31) wsum[w] = inc;
    if (tid == 0) { sNin = 0; sNtie = 0; sT = 0; sNeed = 0; }
    if (tid < 80) ccnt[tid] = 0;
    __syncthreads();
    if (w == 0) {
        int v = wsum[lane];
        #pragma unroll
        for (int off = 1; off < 32; off <<= 1) {
            int n = __shfl_up_sync(FULL, v, off);
            if (lane >= off) v += n;
        }
        wsum[lane] = v;
    }
    __syncthreads();
    int wbase = w ? wsum[w - 1] : 0;
    int incl = wbase + inc, excl = incl - s;
    int total = wsum[31];
    if (tid == 0) sAllin = (total <= K);
    if (total > K && excl < K && incl >= K) {     // unique crossing thread
        int acc = excl, tb = lo, hv = 0;
        for (int b = hi - 1; b >= lo; b--) {
            hv = g_hist[seg][b]; acc += hv;
            if (acc >= K) { tb = b; break; }
        }
        sT = tb;
        sNeed = K - (acc - hv);
    }
    __syncthreads();
    int T = sT, allin = sAllin, need = sNeed;
    if (tid == 0) {
        if (allin) { sCutIn = 0x80000001u; sCutTie = 0x80000001u; }
        else       { sCutIn = cut_for(T + 1); sCutTie = cut_for(T); }
    }
    for (int i = tid; i < NBIN; i += 1024) g_hist[seg][i] = 0;   // next replay
    __syncthreads();
    unsigned cutIn = sCutIn, cutTie = sCutTie;
    if (allin) cutTie = cutIn;                    // tie set empty

    // --- Phase B: vectorized gather, 8 keys/thread/iter (4 rounds) ---
    const ulonglong2* keys2 = (const ulonglong2*)keys;
    const int NP = NROW / 2;                      // 12600
    const unsigned lmlt = (1u << lane) - 1u;
    for (int it = 0; it < 4; it++) {
        ulonglong2 kk[4];
        unsigned hw4[4][2];
        bool in[4][2];
        #pragma unroll
        for (int q = 0; q < 4; q++) {
            int i = it * 4096 + q * 1024 + tid;
            if (i < NP) kk[q] = keys2[i]; else { kk[q].x = 0; kk[q].y = 0; }
            hw4[q][0] = (unsigned)(kk[q].x >> 32);
            hw4[q][1] = (unsigned)(kk[q].y >> 32);
            in[q][0] = hw4[q][0] >= cutIn;
            in[q][1] = hw4[q][1] >= cutIn;
        }
        unsigned m[4][2];
        int tot = 0;
        #pragma unroll
        for (int q = 0; q < 4; q++) {
            m[q][0] = __ballot_sync(FULL, in[q][0]);
            m[q][1] = __ballot_sync(FULL, in[q][1]);
            tot += __popc(m[q][0]) + __popc(m[q][1]);
        }
        if (tot) {
            unsigned any = 0;
            #pragma unroll
            for (int q = 0; q < 4; q++) any |= m[q][0] | m[q][1];
            int leader = __ffs(any) - 1, base = 0;
            if (lane == leader) base = atomicAdd(&sNin, tot);
            base = __shfl_sync(FULL, base, leader);
            #pragma unroll
            for (int q = 0; q < 4; q++) {
                if (in[q][0]) U.sel.skey[base + __popc(m[q][0] & lmlt)] = kk[q].x;
                base += __popc(m[q][0]);
                if (in[q][1]) U.sel.skey[base + __popc(m[q][1] & lmlt)] = kk[q].y;
                base += __popc(m[q][1]);
            }
        }
        #pragma unroll
        for (int q = 0; q < 4; q++) {
            if (!in[q][0] && hw4[q][0] >= cutTie) {
                int p = atomicAdd(&sNtie, 1); if (p < 1024) U.sel.tie[p] = kk[q].x;
            }
            if (!in[q][1] && hw4[q][1] >= cutTie) {
                int p = atomicAdd(&sNtie, 1); if (p < 1024) U.sel.tie[p] = kk[q].y;
            }
        }
    }
    __syncthreads();
    int nin = sNin;
    int S = nin;
    if (!allin && need > 0) {
        // --- tie resolve by rank-counting (keys distinct, no sort) ---
        int nt = sNtie; if (nt > 1024) nt = 1024;
        if (tid < nt) {
            unsigned long long k = U.sel.tie[tid];
            int rank = 0;
            for (int j = 0; j < nt; j++) rank += (U.sel.tie[j] > k);
            if (rank < need) U.sel.skey[nin + rank] = k;
        }
        S = nin + need;
    }
    __syncthreads();

    // --- Phase C: per-thread decode + exact earliest product-argmax ---
    if (tid < S) {
        unsigned long long key = U.sel.skey[tid];
        int idx = 32767 - (int)((key >> 7) & 32767u);
        const float* rp = src + (size_t)idx * 85;
        float cx = rp[0], cy = rp[1], ww2 = rp[2], hh2 = rp[3];
        float obj = rp[4];
        float bv = -1.0f; int cls = 0;
        #pragma unroll 8
        for (int c = 5; c < 85; c++) {
            float x = __fmul_rn(rp[c], obj);
            if (x > bv) { bv = x; cls = c - 5; }        // strict > keeps earliest
        }
        float hw = __fmul_rn(ww2, 0.5f), hh = __fmul_rn(hh2, 0.5f);
        float4 pb4, ob;
        pb4.x = __fsub_rn(cx, hw); pb4.y = __fsub_rn(cy, hh);
        pb4.z = __fadd_rn(cx, hw); pb4.w = __fadd_rn(cy, hh);
        float off = (float)cls * 4096.0f;
        ob.x = __fadd_rn(pb4.x, off); ob.y = __fadd_rn(pb4.y, off);
        ob.z = __fadd_rn(pb4.z, off); ob.w = __fadd_rn(pb4.w, off);
        g_box[which][img][tid] = pb4;
        g_cls[which][img][tid] = (unsigned char)cls;
        U.sel.obox[tid] = ob;
        keepc[tid] = 1;
        int p = atomicAdd(&ccnt[cls], 1);
        if (p < 64) U.sel.clslist[cls * 64 + p] = (short)tid;
        else        g_keep[which][img][tid] = 1;   // overflow: treat as kept
    }
    for (int i = S + tid; i < K; i += 1024) g_keep[which][img][i] = 0;
    __syncthreads();

    // --- Phase D: per-class NMS, one warp per class ---
    for (int c = w; c < 80; c += 32) {
        int m = ccnt[c]; if (m > 64) m = 64;
        int base2 = c * 64;
        if (m == 0) continue;
        if (m == 1) {
            if (lane == 0) { int id = U.sel.clslist[base2]; g_keep[which][img][id] = 1; }
            continue;
        }
        if (m <= 32) {
            int id = (lane < m) ? U.sel.clslist[base2 + lane] : -1;
            unsigned long long kk = (lane < m) ? U.sel.skey[id] : 0ull;
            unsigned hi32 = (unsigned)(kk >> 32), lo32 = (unsigned)kk;
            int rank = 0;
            for (int j = 0; j < m; j++) {
                unsigned hj = __shfl_sync(FULL, hi32, j);
                unsigned lj = __shfl_sync(FULL, lo32, j);
                if (hj > hi32 || (hj == hi32 && lj > lo32)) rank++;
            }
            if (lane < m) U.sel.clslist[base2 + rank] = (short)id;
            __syncwarp();
            id = (lane < m) ? U.sel.clslist[base2 + lane] : -1;
            float4 B = (lane < m) ? U.sel.obox[id] : make_float4(0.f, 0.f, 0.f, 0.f);
            unsigned keepb = (m >= 32) ? FULL : ((1u << m) - 1u);
            for (int a = 0; a < m - 1; a++) {
                if ((keepb >> a) & 1u) {
                    float4 A;
                    A.x = __shfl_sync(FULL, B.x, a);
                    A.y = __shfl_sync(FULL, B.y, a);
                    A.z = __shfl_sync(FULL, B.z, a);
                    A.w = __shfl_sync(FULL, B.w, a);
                    bool sup = (lane > a) && (lane < m) && ((keepb >> lane) & 1u)
                               && (iou_rn(A, B) > 0.45f);
                    keepb &= ~__ballot_sync(FULL, sup);
                }
            }
            if (lane < m) g_keep[which][img][id] = (unsigned char)((keepb >> lane) & 1u);
        } else {
            if (lane == 0) {
                for (int i2 = 1; i2 < m; i2++) {
                    short v = U.sel.clslist[base2 + i2];
                    unsigned long long kv = U.sel.skey[v];
                    int j2 = i2 - 1;
                    while (j2 >= 0 && U.sel.skey[U.sel.clslist[base2 + j2]] < kv) {
                        U.sel.clslist[base2 + j2 + 1] = U.sel.clslist[base2 + j2]; j2--;
                    }
                    U.sel.clslist[base2 + j2 + 1] = v;
                }
            }
            __syncwarp();
            for (int a = 0; a < m - 1; a++) {
                int ta = U.sel.clslist[base2 + a];
                if (keepc[ta]) {
                    float4 A = U.sel.obox[ta];
                    for (int b = a + 1 + lane; b < m; b += 32) {
                        int tb = U.sel.clslist[base2 + b];
                        if (keepc[tb] && iou_rn(A, U.sel.obox[tb]) > 0.45f) keepc[tb] = 0;
                    }
                }
                __syncwarp();
            }
            for (int b = lane; b < m; b += 32) {
                int tb = U.sel.clslist[base2 + b];
                g_keep[which][img][tb] = keepc[tb];
            }
        }
    }
    __syncthreads();

    // --- Phase E: handshake + fused loss ---
    if (which == 1) {                         // patch: publish and exit
        __threadfence();
        if (tid == 0) atomicExch(&g_flag[img], 1);
        return;
    }

    int myk = 0, myc2 = 0;
    float4 myb = make_float4(0.f, 0.f, 0.f, 0.f);
    if (tid < KC) {
        myk  = g_keep[0][img][tid];
        myc2 = g_cls [0][img][tid];
        myb  = g_box [0][img][tid];
    }
    if (tid == 0) { while (atomicAdd(&g_flag[img], 0) == 0) {} }
    __syncthreads();                          // flag seen -> patch data visible
    if (tid < 80) ccnt[tid] = 0;
    __syncthreads();

    {
        int pk = g_keep[1][img][tid];
        int pc = g_cls [1][img][tid];
        float4 pb = g_box[1][img][tid];
        U.loss.pdiv[tid] = make_float4(__fdiv_rn(pb.x, 640.0f), __fdiv_rn(pb.y, 640.0f),
                                       __fdiv_rn(pb.z, 640.0f), __fdiv_rn(pb.w, 640.0f));
        if (pk) {
            int p = atomicAdd(&ccnt[pc], 1);
            if (p < 128) U.loss.plist[pc * 128 + p] = (short)tid;
        }
    }
    __syncthreads();

    float ss = 0.0f, nn = 0.0f;
    if (tid < KC && myk) {
        nn = 1.0f;
        float4 cd = make_float4(__fdiv_rn(myb.x, 640.0f), __fdiv_rn(myb.y, 640.0f),
                                __fdiv_rn(myb.z, 640.0f), __fdiv_rn(myb.w, 640.0f));
        float tm = 0.0f;
        int m = ccnt[myc2]; if (m > 128) m = 128;
        int base2 = myc2 * 128;
        for (int b2 = 0; b2 < m; b2++)
            tm = fmaxf(tm, iou_rn(cd, U.loss.pdiv[U.loss.plist[base2 + b2]]));
        ss = tm;
    }
    #pragma unroll
    for (int off = 16; off; off >>= 1) {
        ss += __shfl_down_sync(FULL, ss, off);
        nn += __shfl_down_sync(FULL, nn, off);
    }
    if (lane == 0) { rs[w] = ss; rn2[w] = nn; }
    __syncthreads();
    if (tid == 0) {
        float Sm = 0.0f, Nm = 0.0f;
        #pragma unroll
        for (int i = 0; i < 32; i++) { Sm += rs[i]; Nm += rn2[i]; }
        g_s[img] = Sm; g_n[img] = Nm;
        __threadfence();
        int old = atomicAdd(&g_cnt, 1);
        if (old == BIMG - 1) {
            float tot = 0.0f, cnt = 0.0f;
            for (int i = 0; i < BIMG; i++) { tot += g_s[i]; cnt += g_n[i]; }
            out[0] = (cnt > 0.0f) ? __fsub_rn(1.0f, __fdiv_rn(tot, fmaxf(cnt, 1.0f)))
                                  : 1.0f;
            g_cnt = 0;
        }
        g_flag[img] = 0;                       // reset for next replay
    }
}

// ---------------- launch ----------------------------------------------------
extern "C" void kernel_launch(void* const* d_in, const int* in_sizes, int n_in,
                              void* d_out, int out_size) {
    const float* clean = (const float*)d_in[0];
    const float* patch = (const float*)d_in[1];

    dim3 sgrid(NTILE, 16);                     // 225 x 16 tiles
    k_score<<<sgrid, 128>>>(clean, patch);
    k_select<<<16, 1024>>>(clean, patch, (float*)d_out);
}

// round 11
// speedup vs baseline: 1.1908x; 1.1377x over previous
#include <cuda_runtime.h>

#define FULL 0xFFFFFFFFu
static const int NROW = 25200;
static const int BIMG = 8;
static const int NBIN = 2048;
static const int KC   = 512;
static const int KP   = 1024;
static const int TILE = 112;               // 25200 = 225 * 112
static const int NTILE = NROW / TILE;      // 225

// ---------------- global scratch (static __device__, no allocation) -------
__device__ __align__(16) unsigned long long g_keys[2][BIMG][NROW];
__device__ int            g_hist[16][NBIN];
__device__ float4         g_box [2][BIMG][KP];
__device__ unsigned char  g_cls [2][BIMG][KP];
__device__ unsigned char  g_keep[2][BIMG][KP];
__device__ int            g_flag[BIMG];    // patch segment done flags
__device__ float          g_s[BIMG], g_n[BIMG];
__device__ int            g_cnt;

__device__ __forceinline__ float iou_rn(float4 a, float4 b) {
    float tlx = fmaxf(a.x, b.x), tly = fmaxf(a.y, b.y);
    float brx = fminf(a.z, b.z), bry = fminf(a.w, b.w);
    float w = fmaxf(__fsub_rn(brx, tlx), 0.0f);
    float h = fmaxf(__fsub_rn(bry, tly), 0.0f);
    float inter = __fmul_rn(w, h);
    float aa = __fmul_rn(__fsub_rn(a.z, a.x), __fsub_rn(a.w, a.y));
    float ab = __fmul_rn(__fsub_rn(b.z, b.x), __fsub_rn(b.w, b.y));
    float uni = __fsub_rn(__fadd_rn(aa, ab), inter);
    uni = (uni > 0.0f) ? uni : 1.0f;
    return __fdiv_rn(inter, uni);
}

__device__ __forceinline__ int binof(float conf) {
    int b = (int)(__fmul_rn(conf, 2048.0f));
    return b > NBIN - 1 ? NBIN - 1 : (b < 0 ? 0 : b);
}

// biased high-word of the smallest positive float whose bin >= B (exact).
__device__ __forceinline__ unsigned cut_for(int B) {
    if (B <= 0) return 0x80000001u;
    if (B > NBIN - 1) return 0xFFFFFFFFu;
    float g = (float)B / 2048.0f;
    for (;;) {
        float p = __int_as_float(__float_as_int(g) - 1);
        if ((int)(__fmul_rn(p, 2048.0f)) >= B) g = p; else break;
    }
    return __float_as_uint(g) ^ 0x80000000u;
}

// ---------------- K1: tile-staged score / key / histogram ------------------
// conf = RN(max_c raw * obj): exact (RN-mult by obj>0 monotone). cls found
// lazily (only for rows passing threshold): first c with RN(row[c]*obj)==conf
// == reference earliest-index argmax.
__global__ void __launch_bounds__(128) k_score(const float* __restrict__ clean,
                                               const float* __restrict__ patch) {
    __shared__ float sd[TILE * 85];
    int seg   = blockIdx.y;
    int which = seg >> 3, img = seg & 7;
    int tile  = blockIdx.x;
    const float* base = (which ? patch : clean)
                      + ((size_t)img * NROW + (size_t)tile * TILE) * 85;
    const float4* b4 = (const float4*)base;
    float4* s4 = (float4*)sd;
    const int NV4 = TILE * 85 / 4;                      // 2380
    #pragma unroll 5
    for (int i = threadIdx.x; i < NV4; i += 128) s4[i] = b4[i];
    __syncthreads();

    int tid = threadIdx.x;
    if (tid < TILE) {
        const float* row = sd + tid * 85;
        float obj = row[4];
        float m0 = row[5], m1 = row[6], m2 = row[7], m3 = row[8];
        #pragma unroll
        for (int c = 9; c < 85; c += 4) {
            m0 = fmaxf(m0, row[c]);     m1 = fmaxf(m1, row[c + 1]);
            m2 = fmaxf(m2, row[c + 2]); m3 = fmaxf(m3, row[c + 3]);
        }
        float conf = __fmul_rn(fmaxf(fmaxf(m0, m1), fmaxf(m2, m3)), obj);
        int r = tile * TILE + tid;
        float TH = which ? 0.001f : 0.25f;
        unsigned long long key = 0ull;
        if (obj > TH && conf > TH) {
            int cls = 0;
            for (int c = 5; c < 85; c++) {
                if (__fmul_rn(row[c], obj) == conf) { cls = c - 5; break; }
            }
            unsigned u = __float_as_uint(conf) ^ 0x80000000u;
            key = ((unsigned long long)u << 32)
                | ((unsigned)(32767 - r) << 7) | (unsigned)cls;
            atomicAdd(&g_hist[seg][binof(conf)], 1);
        }
        g_keys[which][img][r] = key;                    // coalesced
    }
}

// ---------------- K2: threshold + gather + tie + NMS + fused loss ----------
__global__ void __launch_bounds__(1024) k_select(const float* __restrict__ clean,
                                                 const float* __restrict__ patch,
                                                 float* __restrict__ out) {
    __shared__ union {
        struct {
            unsigned long long skey[KP];
            unsigned long long tie[1024];
            float4 obox[KP];
            short  clslist[80 * 64];
        } sel;
        struct {
            float4 pdiv[KP];
            short  plist[80 * 128];
        } loss;
    } U;
    __shared__ unsigned char keepc[KP];
    __shared__ int   ccnt[80];
    __shared__ int   wsum[32];
    __shared__ float rs[32], rn2[32];
    __shared__ int   sT, sNeed, sAllin, sNin, sNtie;
    __shared__ unsigned sCutIn, sCutTie;

    int seg = blockIdx.x;
    int which = seg >> 3, img = seg & 7;
    int K = which ? KP : KC;
    const float* src = (which ? patch : clean) + (size_t)img * NROW * 85;
    const unsigned long long* keys = g_keys[which][img];
    int tid = threadIdx.x, lane = tid & 31, w = tid >> 5;

    // --- Phase A: threshold from histogram (descending-bin chunks) ---
    const int CH = NBIN / 1024;                  // 2
    int hi = NBIN - CH * tid, lo = hi - CH;
    int s = g_hist[seg][lo] + g_hist[seg][lo + 1];
    int inc = s;
    #pragma unroll
    for (int off = 1; off < 32; off <<= 1) {
        int n = __shfl_up_sync(FULL, inc, off);
        if (lane >= off) inc += n;
    }
    if (lane == 31) wsum[w] = inc;
    if (tid == 0) { sNin = 0; sNtie = 0; sT = 0; sNeed = 0; }
    if (tid < 80) ccnt[tid] = 0;
    __syncthreads();
    if (w == 0) {
        int v = wsum[lane];
        #pragma unroll
        for (int off = 1; off < 32; off <<= 1) {
            int n = __shfl_up_sync(FULL, v, off);
            if (lane >= off) v += n;
        }
        wsum[lane] = v;
    }
    __syncthreads();
    int wbase = w ? wsum[w - 1] : 0;
    int incl = wbase + inc, excl = incl - s;
    int total = wsum[31];
    if (tid == 0) sAllin = (total <= K);
    if (total > K && excl < K && incl >= K) {     // unique crossing thread
        int acc = excl, tb = lo, hv = 0;
        for (int b = hi - 1; b >= lo; b--) {
            hv = g_hist[seg][b]; acc += hv;
            if (acc >= K) { tb = b; break; }
        }
        sT = tb;
        sNeed = K - (acc - hv);
    }
    __syncthreads();
    int T = sT, allin = sAllin, need = sNeed;
    if (tid == 0) {
        if (allin) { sCutIn = 0x80000001u; sCutTie = 0x80000001u; }
        else       { sCutIn = cut_for(T + 1); sCutTie = cut_for(T); }
    }
    for (int i = tid; i < NBIN; i += 1024) g_hist[seg][i] = 0;   // next replay
    __syncthreads();
    unsigned cutIn = sCutIn, cutTie = sCutTie;
    if (allin) cutTie = cutIn;                    // tie set empty

    // --- Phase B: vectorized gather, 8 keys/thread/iter (4 rounds) ---
    const ulonglong2* keys2 = (const ulonglong2*)keys;
    const int NP = NROW / 2;                      // 12600
    const unsigned lmlt = (1u << lane) - 1u;
    for (int it = 0; it < 4; it++) {
        ulonglong2 kk[4];
        unsigned hw4[4][2];
        bool in[4][2];
        #pragma unroll
        for (int q = 0; q < 4; q++) {
            int i = it * 4096 + q * 1024 + tid;
            if (i < NP) kk[q] = keys2[i]; else { kk[q].x = 0; kk[q].y = 0; }
            hw4[q][0] = (unsigned)(kk[q].x >> 32);
            hw4[q][1] = (unsigned)(kk[q].y >> 32);
            in[q][0] = hw4[q][0] >= cutIn;
            in[q][1] = hw4[q][1] >= cutIn;
        }
        unsigned m[4][2];
        int tot = 0;
        #pragma unroll
        for (int q = 0; q < 4; q++) {
            m[q][0] = __ballot_sync(FULL, in[q][0]);
            m[q][1] = __ballot_sync(FULL, in[q][1]);
            tot += __popc(m[q][0]) + __popc(m[q][1]);
        }
        if (tot) {
            unsigned any = 0;
            #pragma unroll
            for (int q = 0; q < 4; q++) any |= m[q][0] | m[q][1];
            int leader = __ffs(any) - 1, base = 0;
            if (lane == leader) base = atomicAdd(&sNin, tot);
            base = __shfl_sync(FULL, base, leader);
            #pragma unroll
            for (int q = 0; q < 4; q++) {
                if (in[q][0]) U.sel.skey[base + __popc(m[q][0] & lmlt)] = kk[q].x;
                base += __popc(m[q][0]);
                if (in[q][1]) U.sel.skey[base + __popc(m[q][1] & lmlt)] = kk[q].y;
                base += __popc(m[q][1]);
            }
        }
        #pragma unroll
        for (int q = 0; q < 4; q++) {
            if (!in[q][0] && hw4[q][0] >= cutTie) {
                int p = atomicAdd(&sNtie, 1); if (p < 1024) U.sel.tie[p] = kk[q].x;
            }
            if (!in[q][1] && hw4[q][1] >= cutTie) {
                int p = atomicAdd(&sNtie, 1); if (p < 1024) U.sel.tie[p] = kk[q].y;
            }
        }
    }
    __syncthreads();
    int nin = sNin;
    int S = nin;
    if (!allin && need > 0) {
        // --- tie resolve by rank-counting (keys distinct, no sort) ---
        int nt = sNtie; if (nt > 1024) nt = 1024;
        if (tid < nt) {
            unsigned long long k = U.sel.tie[tid];
            int rank = 0;
            for (int j = 0; j < nt; j++) rank += (U.sel.tie[j] > k);
            if (rank < need) U.sel.skey[nin + rank] = k;
        }
        S = nin + need;
    }
    __syncthreads();

    // --- Phase C: per-thread decode (cls from key; 5 loads per row) ---
    if (tid < S) {
        unsigned long long key = U.sel.skey[tid];
        unsigned lo32 = (unsigned)key;
        int cls = (int)(lo32 & 127u);
        int idx = 32767 - (int)((lo32 >> 7) & 32767u);
        const float* rp = src + (size_t)idx * 85;
        float cx = rp[0], cy = rp[1], ww2 = rp[2], hh2 = rp[3];
        float hw = __fmul_rn(ww2, 0.5f), hh = __fmul_rn(hh2, 0.5f);
        float4 pb4, ob;
        pb4.x = __fsub_rn(cx, hw); pb4.y = __fsub_rn(cy, hh);
        pb4.z = __fadd_rn(cx, hw); pb4.w = __fadd_rn(cy, hh);
        float off = (float)cls * 4096.0f;
        ob.x = __fadd_rn(pb4.x, off); ob.y = __fadd_rn(pb4.y, off);
        ob.z = __fadd_rn(pb4.z, off); ob.w = __fadd_rn(pb4.w, off);
        g_box[which][img][tid] = pb4;
        g_cls[which][img][tid] = (unsigned char)cls;
        U.sel.obox[tid] = ob;
        keepc[tid] = 1;
        int p = atomicAdd(&ccnt[cls], 1);
        if (p < 64) U.sel.clslist[cls * 64 + p] = (short)tid;
        else        g_keep[which][img][tid] = 1;   // overflow: treat as kept
    }
    for (int i = S + tid; i < K; i += 1024) g_keep[which][img][i] = 0;
    __syncthreads();

    // --- Phase D: per-class NMS, one warp per class ---
    for (int c = w; c < 80; c += 32) {
        int m = ccnt[c]; if (m > 64) m = 64;
        int base2 = c * 64;
        if (m == 0) continue;
        if (m == 1) {
            if (lane == 0) { int id = U.sel.clslist[base2]; g_keep[which][img][id] = 1; }
            continue;
        }
        if (m <= 32) {
            int id = (lane < m) ? U.sel.clslist[base2 + lane] : -1;
            unsigned long long kk = (lane < m) ? U.sel.skey[id] : 0ull;
            unsigned hi32 = (unsigned)(kk >> 32), lo32 = (unsigned)kk;
            int rank = 0;
            for (int j = 0; j < m; j++) {
                unsigned hj = __shfl_sync(FULL, hi32, j);
                unsigned lj = __shfl_sync(FULL, lo32, j);
                if (hj > hi32 || (hj == hi32 && lj > lo32)) rank++;
            }
            if (lane < m) U.sel.clslist[base2 + rank] = (short)id;
            __syncwarp();
            id = (lane < m) ? U.sel.clslist[base2 + lane] : -1;
            float4 B = (lane < m) ? U.sel.obox[id] : make_float4(0.f, 0.f, 0.f, 0.f);
            unsigned keepb = (m >= 32) ? FULL : ((1u << m) - 1u);
            for (int a = 0; a < m - 1; a++) {
                if ((keepb >> a) & 1u) {
                    float4 A;
                    A.x = __shfl_sync(FULL, B.x, a);
                    A.y = __shfl_sync(FULL, B.y, a);
                    A.z = __shfl_sync(FULL, B.z, a);
                    A.w = __shfl_sync(FULL, B.w, a);
                    bool sup = (lane > a) && (lane < m) && ((keepb >> lane) & 1u)
                               && (iou_rn(A, B) > 0.45f);
                    keepb &= ~__ballot_sync(FULL, sup);
                }
            }
            if (lane < m) g_keep[which][img][id] = (unsigned char)((keepb >> lane) & 1u);
        } else {
            if (lane == 0) {
                for (int i2 = 1; i2 < m; i2++) {
                    short v = U.sel.clslist[base2 + i2];
                    unsigned long long kv = U.sel.skey[v];
                    int j2 = i2 - 1;
                    while (j2 >= 0 && U.sel.skey[U.sel.clslist[base2 + j2]] < kv) {
                        U.sel.clslist[base2 + j2 + 1] = U.sel.clslist[base2 + j2]; j2--;
                    }
                    U.sel.clslist[base2 + j2 + 1] = v;
                }
            }
            __syncwarp();
            for (int a = 0; a < m - 1; a++) {
                int ta = U.sel.clslist[base2 + a];
                if (keepc[ta]) {
                    float4 A = U.sel.obox[ta];
                    for (int b = a + 1 + lane; b < m; b += 32) {
                        int tb = U.sel.clslist[base2 + b];
                        if (keepc[tb] && iou_rn(A, U.sel.obox[tb]) > 0.45f) keepc[tb] = 0;
                    }
                }
                __syncwarp();
            }
            for (int b = lane; b < m; b += 32) {
                int tb = U.sel.clslist[base2 + b];
                g_keep[which][img][tb] = keepc[tb];
            }
        }
    }
    __syncthreads();

    // --- Phase E: handshake + fused loss ---
    if (which == 1) {                         // patch: publish and exit
        __threadfence();
        if (tid == 0) atomicExch(&g_flag[img], 1);
        return;
    }

    int myk = 0, myc2 = 0;
    float4 myb = make_float4(0.f, 0.f, 0.f, 0.f);
    if (tid < KC) {
        myk  = g_keep[0][img][tid];
        myc2 = g_cls [0][img][tid];
        myb  = g_box [0][img][tid];
    }
    if (tid == 0) { while (atomicAdd(&g_flag[img], 0) == 0) {} }
    __syncthreads();                          // flag seen -> patch data visible
    if (tid < 80) ccnt[tid] = 0;
    __syncthreads();

    {
        int pk = g_keep[1][img][tid];
        int pc = g_cls [1][img][tid];
        float4 pb = g_box[1][img][tid];
        U.loss.pdiv[tid] = make_float4(__fdiv_rn(pb.x, 640.0f), __fdiv_rn(pb.y, 640.0f),
                                       __fdiv_rn(pb.z, 640.0f), __fdiv_rn(pb.w, 640.0f));
        if (pk) {
            int p = atomicAdd(&ccnt[pc], 1);
            if (p < 128) U.loss.plist[pc * 128 + p] = (short)tid;
        }
    }
    __syncthreads();

    float ss = 0.0f, nn = 0.0f;
    if (tid < KC && myk) {
        nn = 1.0f;
        float4 cd = make_float4(__fdiv_rn(myb.x, 640.0f), __fdiv_rn(myb.y, 640.0f),
                                __fdiv_rn(myb.z, 640.0f), __fdiv_rn(myb.w, 640.0f));
        float tm = 0.0f;
        int m = ccnt[myc2]; if (m > 128) m = 128;
        int base2 = myc2 * 128;
        for (int b2 = 0; b2 < m; b2++)
            tm = fmaxf(tm, iou_rn(cd, U.loss.pdiv[U.loss.plist[base2 + b2]]));
        ss = tm;
    }
    #pragma unroll
    for (int off = 16; off; off >>= 1) {
        ss += __shfl_down_sync(FULL, ss, off);
        nn += __shfl_down_sync(FULL, nn, off);
    }
    if (lane == 0) { rs[w] = ss; rn2[w] = nn; }
    __syncthreads();
    if (tid == 0) {
        float Sm = 0.0f, Nm = 0.0f;
        #pragma unroll
        for (int i = 0; i < 32; i++) { Sm += rs[i]; Nm += rn2[i]; }
        g_s[img] = Sm; g_n[img] = Nm;
        __threadfence();
        int old = atomicAdd(&g_cnt, 1);
        if (old == BIMG - 1) {
            float tot = 0.0f, cnt = 0.0f;
            for (int i = 0; i < BIMG; i++) { tot += g_s[i]; cnt += g_n[i]; }
            out[0] = (cnt > 0.0f) ? __fsub_rn(1.0f, __fdiv_rn(tot, fmaxf(cnt, 1.0f)))
                                  : 1.0f;
            g_cnt = 0;
        }
        g_flag[img] = 0;                       // reset for next replay
    }
}

// ---------------- launch ----------------------------------------------------
extern "C" void kernel_launch(void* const* d_in, const int* in_sizes, int n_in,
                              void* d_out, int out_size) {
    const float* clean = (const float*)d_in[0];
    const float* patch = (const float*)d_in[1];

    dim3 sgrid(NTILE, 16);                     // 225 x 16 tiles
    k_score<<<sgrid, 128>>>(clean, patch);
    k_select<<<16, 1024>>>(clean, patch, (float*)d_out);
}

// round 12
// speedup vs baseline: 1.3699x; 1.1504x over previous
#include <cuda_runtime.h>

#define FULL 0xFFFFFFFFu
static const int NROW = 25200;
static const int BIMG = 8;
static const int NBIN = 2048;
static const int KC   = 512;
static const int KP   = 1024;
static const int TILE = 112;               // 25200 = 225 * 112
static const int NTILE = NROW / TILE;      // 225

// ---------------- global scratch (static __device__, no allocation) -------
__device__ __align__(16) unsigned long long g_keys[2][BIMG][NROW];
__device__ int            g_hist[16][NBIN];
__device__ float4         g_box [2][BIMG][KP];
__device__ unsigned char  g_cls [2][BIMG][KP];
__device__ unsigned char  g_keep[2][BIMG][KP];   // only [0] (clean) is published
__device__ int            g_flag[BIMG];    // clean segment done flags
__device__ float          g_tot[2];
__device__ int            g_cnt;

__device__ __forceinline__ float iou_rn(float4 a, float4 b) {
    float tlx = fmaxf(a.x, b.x), tly = fmaxf(a.y, b.y);
    float brx = fminf(a.z, b.z), bry = fminf(a.w, b.w);
    float w = fmaxf(__fsub_rn(brx, tlx), 0.0f);
    float h = fmaxf(__fsub_rn(bry, tly), 0.0f);
    float inter = __fmul_rn(w, h);
    float aa = __fmul_rn(__fsub_rn(a.z, a.x), __fsub_rn(a.w, a.y));
    float ab = __fmul_rn(__fsub_rn(b.z, b.x), __fsub_rn(b.w, b.y));
    float uni = __fsub_rn(__fadd_rn(aa, ab), inter);
    uni = (uni > 0.0f) ? uni : 1.0f;
    return __fdiv_rn(inter, uni);
}

__device__ __forceinline__ int binof(float conf) {
    int b = (int)(__fmul_rn(conf, 2048.0f));
    return b > NBIN - 1 ? NBIN - 1 : (b < 0 ? 0 : b);
}

// biased high-word of the smallest positive float whose bin >= B (exact).
__device__ __forceinline__ unsigned cut_for(int B) {
    if (B <= 0) return 0x80000001u;
    if (B > NBIN - 1) return 0xFFFFFFFFu;
    float g = (float)B / 2048.0f;
    for (;;) {
        float p = __int_as_float(__float_as_int(g) - 1);
        if ((int)(__fmul_rn(p, 2048.0f)) >= B) g = p; else break;
    }
    return __float_as_uint(g) ^ 0x80000000u;
}

// ---------------- K1: tile-staged score / key / histogram ------------------
// MLP-batched staging (9 outstanding LDG.128 per thread). conf via raw max
// (RN-mult by obj>0 monotone => exact); cls lazily for passing rows only.
__global__ void __launch_bounds__(128) k_score(const float* __restrict__ clean,
                                               const float* __restrict__ patch) {
    __shared__ float sd[TILE * 85];
    int seg   = blockIdx.y;
    int which = seg >> 3, img = seg & 7;
    int tile  = blockIdx.x;
    int tid   = threadIdx.x;
    if (seg == 0 && tile == 0 && tid == 0) { g_tot[0] = 0.0f; g_tot[1] = 0.0f; }
    const float* base = (which ? patch : clean)
                      + ((size_t)img * NROW + (size_t)tile * TILE) * 85;
    const float4* b4 = (const float4*)base;
    float4* s4 = (float4*)sd;

    {   // 2380 float4 = 18*128 + 76
        float4 r[9];
        #pragma unroll
        for (int k = 0; k < 9; k++) r[k] = b4[tid + k * 128];
        #pragma unroll
        for (int k = 0; k < 9; k++) s4[tid + k * 128] = r[k];
        #pragma unroll
        for (int k = 0; k < 9; k++) r[k] = b4[tid + (9 + k) * 128];
        #pragma unroll
        for (int k = 0; k < 9; k++) s4[tid + (9 + k) * 128] = r[k];
        if (tid < 76) s4[tid + 2304] = b4[tid + 2304];
    }
    __syncthreads();

    if (tid < TILE) {
        const float* row = sd + tid * 85;
        float obj = row[4];
        float m0 = row[5], m1 = row[6], m2 = row[7], m3 = row[8];
        #pragma unroll
        for (int c = 9; c < 85; c += 4) {
            m0 = fmaxf(m0, row[c]);     m1 = fmaxf(m1, row[c + 1]);
            m2 = fmaxf(m2, row[c + 2]); m3 = fmaxf(m3, row[c + 3]);
        }
        float conf = __fmul_rn(fmaxf(fmaxf(m0, m1), fmaxf(m2, m3)), obj);
        int r = tile * TILE + tid;
        float TH = which ? 0.001f : 0.25f;
        unsigned long long key = 0ull;
        if (obj > TH && conf > TH) {
            int cls = 0;
            for (int c = 5; c < 85; c++) {
                if (__fmul_rn(row[c], obj) == conf) { cls = c - 5; break; }
            }
            unsigned u = __float_as_uint(conf) ^ 0x80000000u;
            key = ((unsigned long long)u << 32)
                | ((unsigned)(32767 - r) << 7) | (unsigned)cls;
            atomicAdd(&g_hist[seg][binof(conf)], 1);
        }
        g_keys[which][img][r] = key;                    // coalesced
    }
}

// ---------------- K2: threshold + gather + tie + NMS; patch computes loss ---
__global__ void __launch_bounds__(1024) k_select(const float* __restrict__ clean,
                                                 const float* __restrict__ patch,
                                                 float* __restrict__ out) {
    __shared__ union {
        struct {
            unsigned long long skey[KP];
            unsigned long long tie[1024];
            float4 obox[KP];
            short  clslist[80 * 64];
        } sel;
        struct {
            float4 pdiv[KP];
            short  plist[80 * 128];
        } loss;
    } U;
    __shared__ unsigned char keepc[KP];
    __shared__ unsigned char sclz[KP];
    __shared__ int   ccnt[80];
    __shared__ int   wsum[32];
    __shared__ float rs[32], rn2[32];
    __shared__ int   sT, sNeed, sAllin, sNin, sNtie;
    __shared__ unsigned sCutIn, sCutTie;

    int seg = blockIdx.x;
    int which = seg >> 3, img = seg & 7;
    int K = which ? KP : KC;
    const float* src = (which ? patch : clean) + (size_t)img * NROW * 85;
    const unsigned long long* keys = g_keys[which][img];
    int tid = threadIdx.x, lane = tid & 31, w = tid >> 5;

    // --- Phase A: threshold from histogram (descending-bin chunks) ---
    const int CH = NBIN / 1024;                  // 2
    int hi = NBIN - CH * tid, lo = hi - CH;
    int s = g_hist[seg][lo] + g_hist[seg][lo + 1];
    int inc = s;
    #pragma unroll
    for (int off = 1; off < 32; off <<= 1) {
        int n = __shfl_up_sync(FULL, inc, off);
        if (lane >= off) inc += n;
    }
    if (lane == 31) wsum[w] = inc;
    if (tid == 0) { sNin = 0; sNtie = 0; sT = 0; sNeed = 0; }
    if (tid < 80) ccnt[tid] = 0;
    __syncthreads();
    if (w == 0) {
        int v = wsum[lane];
        #pragma unroll
        for (int off = 1; off < 32; off <<= 1) {
            int n = __shfl_up_sync(FULL, v, off);
            if (lane >= off) v += n;
        }
        wsum[lane] = v;
    }
    __syncthreads();
    int wbase = w ? wsum[w - 1] : 0;
    int incl = wbase + inc, excl = incl - s;
    int total = wsum[31];
    if (tid == 0) sAllin = (total <= K);
    if (total > K && excl < K && incl >= K) {     // unique crossing thread
        int acc = excl, tb = lo, hv = 0;
        for (int b = hi - 1; b >= lo; b--) {
            hv = g_hist[seg][b]; acc += hv;
            if (acc >= K) { tb = b; break; }
        }
        sT = tb;
        sNeed = K - (acc - hv);
    }
    __syncthreads();
    int T = sT, allin = sAllin, need = sNeed;
    if (tid == 0) {
        if (allin) { sCutIn = 0x80000001u; sCutTie = 0x80000001u; }
        else       { sCutIn = cut_for(T + 1); sCutTie = cut_for(T); }
    }
    for (int i = tid; i < NBIN; i += 1024) g_hist[seg][i] = 0;   // next replay
    __syncthreads();
    unsigned cutIn = sCutIn, cutTie = sCutTie;
    if (allin) cutTie = cutIn;                    // tie set empty

    // --- Phase B: vectorized gather, 8 keys/thread/iter (4 rounds) ---
    const ulonglong2* keys2 = (const ulonglong2*)keys;
    const int NP = NROW / 2;                      // 12600
    const unsigned lmlt = (1u << lane) - 1u;
    for (int it = 0; it < 4; it++) {
        ulonglong2 kk[4];
        unsigned hw4[4][2];
        bool in[4][2];
        #pragma unroll
        for (int q = 0; q < 4; q++) {
            int i = it * 4096 + q * 1024 + tid;
            if (i < NP) kk[q] = keys2[i]; else { kk[q].x = 0; kk[q].y = 0; }
            hw4[q][0] = (unsigned)(kk[q].x >> 32);
            hw4[q][1] = (unsigned)(kk[q].y >> 32);
            in[q][0] = hw4[q][0] >= cutIn;
            in[q][1] = hw4[q][1] >= cutIn;
        }
        unsigned m[4][2];
        int tot = 0;
        #pragma unroll
        for (int q = 0; q < 4; q++) {
            m[q][0] = __ballot_sync(FULL, in[q][0]);
            m[q][1] = __ballot_sync(FULL, in[q][1]);
            tot += __popc(m[q][0]) + __popc(m[q][1]);
        }
        if (tot) {
            unsigned any = 0;
            #pragma unroll
            for (int q = 0; q < 4; q++) any |= m[q][0] | m[q][1];
            int leader = __ffs(any) - 1, base = 0;
            if (lane == leader) base = atomicAdd(&sNin, tot);
            base = __shfl_sync(FULL, base, leader);
            #pragma unroll
            for (int q = 0; q < 4; q++) {
                if (in[q][0]) U.sel.skey[base + __popc(m[q][0] & lmlt)] = kk[q].x;
                base += __popc(m[q][0]);
                if (in[q][1]) U.sel.skey[base + __popc(m[q][1] & lmlt)] = kk[q].y;
                base += __popc(m[q][1]);
            }
        }
        #pragma unroll
        for (int q = 0; q < 4; q++) {
            if (!in[q][0] && hw4[q][0] >= cutTie) {
                int p = atomicAdd(&sNtie, 1); if (p < 1024) U.sel.tie[p] = kk[q].x;
            }
            if (!in[q][1] && hw4[q][1] >= cutTie) {
                int p = atomicAdd(&sNtie, 1); if (p < 1024) U.sel.tie[p] = kk[q].y;
            }
        }
    }
    __syncthreads();
    int nin = sNin;
    int S = nin;
    if (!allin && need > 0) {
        // tie resolve by rank-counting (keys distinct, no sort)
        int nt = sNtie; if (nt > 1024) nt = 1024;
        if (tid < nt) {
            unsigned long long k = U.sel.tie[tid];
            int rank = 0;
            for (int j = 0; j < nt; j++) rank += (U.sel.tie[j] > k);
            if (rank < need) U.sel.skey[nin + rank] = k;
        }
        S = nin + need;
    }
    __syncthreads();

    // --- Phase C: per-thread decode (cls from key; 5 loads per row) ---
    if (tid < S) {
        unsigned long long key = U.sel.skey[tid];
        unsigned lo32 = (unsigned)key;
        int cls = (int)(lo32 & 127u);
        int idx = 32767 - (int)((lo32 >> 7) & 32767u);
        const float* rp = src + (size_t)idx * 85;
        float cx = rp[0], cy = rp[1], ww2 = rp[2], hh2 = rp[3];
        float hw = __fmul_rn(ww2, 0.5f), hh = __fmul_rn(hh2, 0.5f);
        float4 pb4, ob;
        pb4.x = __fsub_rn(cx, hw); pb4.y = __fsub_rn(cy, hh);
        pb4.z = __fadd_rn(cx, hw); pb4.w = __fadd_rn(cy, hh);
        float off = (float)cls * 4096.0f;
        ob.x = __fadd_rn(pb4.x, off); ob.y = __fadd_rn(pb4.y, off);
        ob.z = __fadd_rn(pb4.z, off); ob.w = __fadd_rn(pb4.w, off);
        g_box[which][img][tid] = pb4;
        g_cls[which][img][tid] = (unsigned char)cls;
        U.sel.obox[tid] = ob;
        keepc[tid] = 1;
        sclz[tid]  = (unsigned char)cls;
        int p = atomicAdd(&ccnt[cls], 1);
        if (p < 64) U.sel.clslist[cls * 64 + p] = (short)tid;
        else if (which == 0) g_keep[0][img][tid] = 1;  // overflow: kept
    } else {
        keepc[tid] = 0;
    }
    if (which == 0)
        for (int i = S + tid; i < K; i += 1024) g_keep[0][img][i] = 0;
    __syncthreads();

    // --- Phase D: per-class NMS, one warp per class (broadcast-smem) ---
    for (int c = w; c < 80; c += 32) {
        int m = ccnt[c]; if (m > 64) m = 64;
        int base2 = c * 64;
        if (m == 0) continue;
        if (m == 1) {
            if (which == 0 && lane == 0)
                g_keep[0][img][U.sel.clslist[base2]] = 1;
            continue;
        }
        if (m <= 32) {
            int id = (lane < m) ? U.sel.clslist[base2 + lane] : -1;
            unsigned long long myk = (lane < m) ? U.sel.skey[id] : 0ull;
            int rank = 0;
            for (int j = 0; j < m; j++) {                  // broadcast LDS
                unsigned long long kj = U.sel.skey[U.sel.clslist[base2 + j]];
                rank += (kj > myk);
            }
            if (lane < m) U.sel.clslist[base2 + rank] = (short)id;
            __syncwarp();
            int ids = (lane < m) ? U.sel.clslist[base2 + lane] : -1;
            float4 B = (lane < m) ? U.sel.obox[ids] : make_float4(0.f, 0.f, 0.f, 0.f);
            unsigned keepb = (m >= 32) ? FULL : ((1u << m) - 1u);
            for (int a = 0; a < m - 1; a++) {
                if ((keepb >> a) & 1u) {
                    float4 A = U.sel.obox[U.sel.clslist[base2 + a]];  // broadcast
                    bool sup = (lane > a) && (lane < m) && ((keepb >> lane) & 1u)
                               && (iou_rn(A, B) > 0.45f);
                    keepb &= ~__ballot_sync(FULL, sup);
                }
            }
            if (lane < m) {
                unsigned char kb = (unsigned char)((keepb >> lane) & 1u);
                keepc[ids] = kb;
                if (which == 0) g_keep[0][img][ids] = kb;
            }
        } else {
            if (lane == 0) {
                for (int i2 = 1; i2 < m; i2++) {
                    short v = U.sel.clslist[base2 + i2];
                    unsigned long long kv = U.sel.skey[v];
                    int j2 = i2 - 1;
                    while (j2 >= 0 && U.sel.skey[U.sel.clslist[base2 + j2]] < kv) {
                        U.sel.clslist[base2 + j2 + 1] = U.sel.clslist[base2 + j2]; j2--;
                    }
                    U.sel.clslist[base2 + j2 + 1] = v;
                }
            }
            __syncwarp();
            for (int a = 0; a < m - 1; a++) {
                int ta = U.sel.clslist[base2 + a];
                if (keepc[ta]) {
                    float4 A = U.sel.obox[ta];
                    for (int b = a + 1 + lane; b < m; b += 32) {
                        int tb = U.sel.clslist[base2 + b];
                        if (keepc[tb] && iou_rn(A, U.sel.obox[tb]) > 0.45f) keepc[tb] = 0;
                    }
                }
                __syncwarp();
            }
            if (which == 0)
                for (int b = lane; b < m; b += 32) {
                    int tb = U.sel.clslist[base2 + b];
                    g_keep[0][img][tb] = keepc[tb];
                }
        }
    }
    __syncthreads();

    // --- Phase E: clean publishes; patch waits + computes loss ---
    if (which == 0) {
        __threadfence();
        if (tid == 0) atomicExch(&g_flag[img], 1);
        return;
    }

    if (tid == 0) { while (atomicAdd(&g_flag[img], 0) == 0) {} }
    __syncthreads();                           // clean data now visible
    if (tid < 80) ccnt[tid] = 0;
    __syncthreads();                           // safe to overlay union

    {   // patch class lists from own smem state; boxes from own (L2-hot) writes
        float4 pb = g_box[1][img][tid];
        U.loss.pdiv[tid] = make_float4(__fdiv_rn(pb.x, 640.0f), __fdiv_rn(pb.y, 640.0f),
                                       __fdiv_rn(pb.z, 640.0f), __fdiv_rn(pb.w, 640.0f));
        if (keepc[tid]) {
            int c = sclz[tid];
            int p = atomicAdd(&ccnt[c], 1);
            if (p < 128) U.loss.plist[c * 128 + p] = (short)tid;
        }
    }
    __syncthreads();

    float ss = 0.0f, nn = 0.0f;
    if (tid < KC && g_keep[0][img][tid]) {
        nn = 1.0f;
        int c = g_cls[0][img][tid];
        float4 cb = g_box[0][img][tid];
        float4 cd = make_float4(__fdiv_rn(cb.x, 640.0f), __fdiv_rn(cb.y, 640.0f),
                                __fdiv_rn(cb.z, 640.0f), __fdiv_rn(cb.w, 640.0f));
        float tm = 0.0f;
        int m = ccnt[c]; if (m > 128) m = 128;
        int base2 = c * 128;
        for (int b2 = 0; b2 < m; b2++)
            tm = fmaxf(tm, iou_rn(cd, U.loss.pdiv[U.loss.plist[base2 + b2]]));
        ss = tm;
    }
    #pragma unroll
    for (int off = 16; off; off >>= 1) {
        ss += __shfl_down_sync(FULL, ss, off);
        nn += __shfl_down_sync(FULL, nn, off);
    }
    if (lane == 0) { rs[w] = ss; rn2[w] = nn; }
    __syncthreads();
    if (tid == 0) {
        float Sm = 0.0f, Nm = 0.0f;
        #pragma unroll
        for (int i = 0; i < 32; i++) { Sm += rs[i]; Nm += rn2[i]; }
        atomicAdd(&g_tot[0], Sm);
        atomicAdd(&g_tot[1], Nm);
        __threadfence();
        int old = atomicAdd(&g_cnt, 1);
        if (old == BIMG - 1) {
            float tot = atomicAdd(&g_tot[0], 0.0f);
            float cnt = atomicAdd(&g_tot[1], 0.0f);
            out[0] = (cnt > 0.0f) ? __fsub_rn(1.0f, __fdiv_rn(tot, fmaxf(cnt, 1.0f)))
                                  : 1.0f;
            g_cnt = 0;
        }
        g_flag[img] = 0;                       // reset for next replay
    }
}

// ---------------- launch ----------------------------------------------------
extern "C" void kernel_launch(void* const* d_in, const int* in_sizes, int n_in,
                              void* d_out, int out_size) {
    const float* clean = (const float*)d_in[0];
    const float* patch = (const float*)d_in[1];

    dim3 sgrid(NTILE, 16);                     // 225 x 16 tiles
    k_score<<<sgrid, 128>>>(clean, patch);
    k_select<<<16, 1024>>>(clean, patch, (float*)d_out);
}

// round 13
// speedup vs baseline: 1.3804x; 1.0076x over previous
#include <cuda_runtime.h>

#define FULL 0xFFFFFFFFu
static const int NROW = 25200;
static const int BIMG = 8;
static const int NBIN = 1024;
static const int KC   = 512;
static const int KP   = 1024;
static const int TILE = 112;               // 25200 = 225 * 112
static const int NTILE = NROW / TILE;      // 225

// ---------------- global scratch (static __device__, no allocation) -------
__device__ __align__(16) unsigned long long g_keys[2][BIMG][NROW];
__device__ int            g_hist[16][NBIN];
__device__ float4         g_box [2][BIMG][KP];
__device__ unsigned char  g_cls [2][BIMG][KP];
__device__ unsigned char  g_keep[2][BIMG][KP];   // only [0] (clean) is published
__device__ int            g_flag[BIMG];    // clean segment done flags
__device__ float          g_tot[2];
__device__ int            g_cnt;

__device__ __forceinline__ float iou_rn(float4 a, float4 b) {
    float tlx = fmaxf(a.x, b.x), tly = fmaxf(a.y, b.y);
    float brx = fminf(a.z, b.z), bry = fminf(a.w, b.w);
    float w = fmaxf(__fsub_rn(brx, tlx), 0.0f);
    float h = fmaxf(__fsub_rn(bry, tly), 0.0f);
    float inter = __fmul_rn(w, h);
    float aa = __fmul_rn(__fsub_rn(a.z, a.x), __fsub_rn(a.w, a.y));
    float ab = __fmul_rn(__fsub_rn(b.z, b.x), __fsub_rn(b.w, b.y));
    float uni = __fsub_rn(__fadd_rn(aa, ab), inter);
    uni = (uni > 0.0f) ? uni : 1.0f;
    return __fdiv_rn(inter, uni);
}

__device__ __forceinline__ int binof(float conf) {
    int b = (int)(__fmul_rn(conf, 1024.0f));
    return b > NBIN - 1 ? NBIN - 1 : (b < 0 ? 0 : b);
}

// biased high-word of the smallest positive float whose bin >= B (exact).
__device__ __forceinline__ unsigned cut_for(int B) {
    if (B <= 0) return 0x80000001u;
    if (B > NBIN - 1) return 0xFFFFFFFFu;
    float g = (float)B / 1024.0f;
    for (;;) {
        float p = __int_as_float(__float_as_int(g) - 1);
        if ((int)(__fmul_rn(p, 1024.0f)) >= B) g = p; else break;
    }
    return __float_as_uint(g) ^ 0x80000000u;
}

// ---------------- K1: tile-staged score / key / histogram ------------------
__global__ void __launch_bounds__(128) k_score(const float* __restrict__ clean,
                                               const float* __restrict__ patch) {
    __shared__ float sd[TILE * 85];
    int seg   = blockIdx.y;
    int which = seg >> 3, img = seg & 7;
    int tile  = blockIdx.x;
    int tid   = threadIdx.x;
    if (seg == 0 && tile == 0 && tid == 0) { g_tot[0] = 0.0f; g_tot[1] = 0.0f; }
    const float* base = (which ? patch : clean)
                      + ((size_t)img * NROW + (size_t)tile * TILE) * 85;
    const float4* b4 = (const float4*)base;
    float4* s4 = (float4*)sd;

    {   // 2380 float4 = 18*128 + 76, MLP-batched
        float4 r[9];
        #pragma unroll
        for (int k = 0; k < 9; k++) r[k] = b4[tid + k * 128];
        #pragma unroll
        for (int k = 0; k < 9; k++) s4[tid + k * 128] = r[k];
        #pragma unroll
        for (int k = 0; k < 9; k++) r[k] = b4[tid + (9 + k) * 128];
        #pragma unroll
        for (int k = 0; k < 9; k++) s4[tid + (9 + k) * 128] = r[k];
        if (tid < 76) s4[tid + 2304] = b4[tid + 2304];
    }
    __syncthreads();

    if (tid < TILE) {
        const float* row = sd + tid * 85;
        float obj = row[4];
        float m0 = row[5], m1 = row[6], m2 = row[7], m3 = row[8];
        #pragma unroll
        for (int c = 9; c < 85; c += 4) {
            m0 = fmaxf(m0, row[c]);     m1 = fmaxf(m1, row[c + 1]);
            m2 = fmaxf(m2, row[c + 2]); m3 = fmaxf(m3, row[c + 3]);
        }
        float conf = __fmul_rn(fmaxf(fmaxf(m0, m1), fmaxf(m2, m3)), obj);
        int r = tile * TILE + tid;
        float TH = which ? 0.001f : 0.25f;
        unsigned long long key = 0ull;
        if (obj > TH && conf > TH) {
            int cls = 0;
            for (int c = 5; c < 85; c++) {
                if (__fmul_rn(row[c], obj) == conf) { cls = c - 5; break; }
            }
            unsigned u = __float_as_uint(conf) ^ 0x80000000u;
            key = ((unsigned long long)u << 32)
                | ((unsigned)(32767 - r) << 7) | (unsigned)cls;
            atomicAdd(&g_hist[seg][binof(conf)], 1);
        }
        g_keys[which][img][r] = key;                    // coalesced
    }
}

// ---------------- K2: threshold + gather + tie + NMS; patch computes loss ---
__global__ void __launch_bounds__(1024) k_select(const float* __restrict__ clean,
                                                 const float* __restrict__ patch,
                                                 float* __restrict__ out) {
    __shared__ union {
        struct {
            unsigned long long skey[KP];
            unsigned long long tie[1024];
            float4 obox[KP];
            short  clslist[80 * 64];
        } sel;
        struct {
            float4 pdiv[KP];
            short  plist[80 * 128];
        } loss;
    } U;
    __shared__ unsigned char keepc[KP];
    __shared__ unsigned char sclz[KP];
    __shared__ int   ccnt[80];
    __shared__ int   wsum[32];
    __shared__ float rs[32], rn2[32];
    __shared__ int   sNeed, sAllin, sNin, sNtie;
    __shared__ unsigned sCutIn, sCutTie;

    int seg = blockIdx.x;
    int which = seg >> 3, img = seg & 7;
    int K = which ? KP : KC;
    const float* src = (which ? patch : clean) + (size_t)img * NROW * 85;
    const unsigned long long* keys = g_keys[which][img];
    int tid = threadIdx.x, lane = tid & 31, w = tid >> 5;

    // --- Phase A: one bin per thread, descending order ---
    int s = g_hist[seg][NBIN - 1 - tid];
    int inc = s;
    #pragma unroll
    for (int off = 1; off < 32; off <<= 1) {
        int n = __shfl_up_sync(FULL, inc, off);
        if (lane >= off) inc += n;
    }
    if (lane == 31) wsum[w] = inc;
    if (tid == 0) { sNin = 0; sNtie = 0; sAllin = 0; sNeed = 0; }
    if (tid < 80) ccnt[tid] = 0;
    __syncthreads();
    if (w == 0) {
        int v = wsum[lane];
        #pragma unroll
        for (int off = 1; off < 32; off <<= 1) {
            int n = __shfl_up_sync(FULL, v, off);
            if (lane >= off) v += n;
        }
        wsum[lane] = v;
    }
    __syncthreads();
    int wbase = w ? wsum[w - 1] : 0;
    int incl = wbase + inc, excl = incl - s;
    int total = wsum[31];
    if (total <= K) {
        if (tid == 0) {
            sAllin = 1; sCutIn = 0x80000001u; sCutTie = 0x80000001u;
        }
    } else if (excl < K && incl >= K) {           // unique crossing thread
        int T = NBIN - 1 - tid;
        sNeed  = K - excl;
        sCutIn = cut_for(T + 1);
        sCutTie = cut_for(T);
    }
    g_hist[seg][tid] = 0;                          // re-zero for next replay
    __syncthreads();
    int allin = sAllin, need = sNeed;
    unsigned cutIn = sCutIn, cutTie = sCutTie;

    // --- Phase B: gather, 5 keys2/thread/round x 3 rounds, scan-based ---
    const ulonglong2* keys2 = (const ulonglong2*)keys;
    const int NP = NROW / 2;                       // 12600
    for (int it = 0; it < 3; it++) {
        ulonglong2 kk[5];
        bool fin[5][2], fti[5][2];
        int cin = 0, cti = 0;
        #pragma unroll
        for (int q = 0; q < 5; q++) {
            int i = it * 5120 + q * 1024 + tid;
            if (i < NP) kk[q] = keys2[i]; else { kk[q].x = 0; kk[q].y = 0; }
            unsigned ha = (unsigned)(kk[q].x >> 32), hb = (unsigned)(kk[q].y >> 32);
            fin[q][0] = ha >= cutIn;             fin[q][1] = hb >= cutIn;
            fti[q][0] = !fin[q][0] && ha >= cutTie;
            fti[q][1] = !fin[q][1] && hb >= cutTie;
            cin += fin[q][0] + fin[q][1];
            cti += fti[q][0] + fti[q][1];
        }
        // warp inclusive scans
        int pin = cin, pti = cti;
        #pragma unroll
        for (int off = 1; off < 32; off <<= 1) {
            int a = __shfl_up_sync(FULL, pin, off);
            int b = __shfl_up_sync(FULL, pti, off);
            if (lane >= off) { pin += a; pti += b; }
        }
        int wtotin = __shfl_sync(FULL, pin, 31);
        int wtotti = __shfl_sync(FULL, pti, 31);
        int bin0 = 0, bti0 = 0;
        if (lane == 31) {
            if (wtotin) bin0 = atomicAdd(&sNin, wtotin);
            if (wtotti) bti0 = atomicAdd(&sNtie, wtotti);
        }
        bin0 = __shfl_sync(FULL, bin0, 31);
        bti0 = __shfl_sync(FULL, bti0, 31);
        int pos  = bin0 + pin - cin;
        int posT = bti0 + pti - cti;
        #pragma unroll
        for (int q = 0; q < 5; q++) {
            if (fin[q][0]) U.sel.skey[pos++] = kk[q].x;
            if (fti[q][0] && posT < 1024) U.sel.tie[posT] = kk[q].x;
            posT += fti[q][0];
            if (fin[q][1]) U.sel.skey[pos++] = kk[q].y;
            if (fti[q][1] && posT < 1024) U.sel.tie[posT] = kk[q].y;
            posT += fti[q][1];
        }
    }
    __syncthreads();
    int nin = sNin;
    int S = nin;
    if (!allin && need > 0) {
        // tie resolve by rank-counting (keys distinct, no sort)
        int nt = sNtie; if (nt > 1024) nt = 1024;
        if (tid < nt) {
            unsigned long long k = U.sel.tie[tid];
            int rank = 0;
            for (int j = 0; j < nt; j++) rank += (U.sel.tie[j] > k);
            if (rank < need) U.sel.skey[nin + rank] = k;
        }
        S = nin + need;
    }
    __syncthreads();

    // --- Phase C: per-thread decode (cls from key; 5 loads per row) ---
    if (tid < S) {
        unsigned long long key = U.sel.skey[tid];
        unsigned lo32 = (unsigned)key;
        int cls = (int)(lo32 & 127u);
        int idx = 32767 - (int)((lo32 >> 7) & 32767u);
        const float* rp = src + (size_t)idx * 85;
        float cx = rp[0], cy = rp[1], ww2 = rp[2], hh2 = rp[3];
        float hw = __fmul_rn(ww2, 0.5f), hh = __fmul_rn(hh2, 0.5f);
        float4 pb4, ob;
        pb4.x = __fsub_rn(cx, hw); pb4.y = __fsub_rn(cy, hh);
        pb4.z = __fadd_rn(cx, hw); pb4.w = __fadd_rn(cy, hh);
        float off = (float)cls * 4096.0f;
        ob.x = __fadd_rn(pb4.x, off); ob.y = __fadd_rn(pb4.y, off);
        ob.z = __fadd_rn(pb4.z, off); ob.w = __fadd_rn(pb4.w, off);
        g_box[which][img][tid] = pb4;
        g_cls[which][img][tid] = (unsigned char)cls;
        U.sel.obox[tid] = ob;
        keepc[tid] = 1;
        sclz[tid]  = (unsigned char)cls;
        int p = atomicAdd(&ccnt[cls], 1);
        if (p < 64) U.sel.clslist[cls * 64 + p] = (short)tid;
        else if (which == 0) g_keep[0][img][tid] = 1;  // overflow: kept
    } else {
        keepc[tid] = 0;
    }
    if (which == 0)
        for (int i = S + tid; i < K; i += 1024) g_keep[0][img][i] = 0;
    __syncthreads();

    // --- Phase D: per-class NMS, one warp per class (broadcast-smem) ---
    for (int c = w; c < 80; c += 32) {
        int m = ccnt[c]; if (m > 64) m = 64;
        int base2 = c * 64;
        if (m == 0) continue;
        if (m == 1) {
            if (which == 0 && lane == 0)
                g_keep[0][img][U.sel.clslist[base2]] = 1;
            continue;
        }
        if (m <= 32) {
            int id = (lane < m) ? U.sel.clslist[base2 + lane] : -1;
            unsigned long long myk = (lane < m) ? U.sel.skey[id] : 0ull;
            int rank = 0;
            for (int j = 0; j < m; j++) {                  // broadcast LDS
                unsigned long long kj = U.sel.skey[U.sel.clslist[base2 + j]];
                rank += (kj > myk);
            }
            if (lane < m) U.sel.clslist[base2 + rank] = (short)id;
            __syncwarp();
            int ids = (lane < m) ? U.sel.clslist[base2 + lane] : -1;
            float4 B = (lane < m) ? U.sel.obox[ids] : make_float4(0.f, 0.f, 0.f, 0.f);
            unsigned keepb = (m >= 32) ? FULL : ((1u << m) - 1u);
            for (int a = 0; a < m - 1; a++) {
                if ((keepb >> a) & 1u) {
                    float4 A = U.sel.obox[U.sel.clslist[base2 + a]];  // broadcast
                    bool sup = (lane > a) && (lane < m) && ((keepb >> lane) & 1u)
                               && (iou_rn(A, B) > 0.45f);
                    keepb &= ~__ballot_sync(FULL, sup);
                }
            }
            if (lane < m) {
                unsigned char kb = (unsigned char)((keepb >> lane) & 1u);
                keepc[ids] = kb;
                if (which == 0) g_keep[0][img][ids] = kb;
            }
        } else {
            if (lane == 0) {
                for (int i2 = 1; i2 < m; i2++) {
                    short v = U.sel.clslist[base2 + i2];
                    unsigned long long kv = U.sel.skey[v];
                    int j2 = i2 - 1;
                    while (j2 >= 0 && U.sel.skey[U.sel.clslist[base2 + j2]] < kv) {
                        U.sel.clslist[base2 + j2 + 1] = U.sel.clslist[base2 + j2]; j2--;
                    }
                    U.sel.clslist[base2 + j2 + 1] = v;
                }
            }
            __syncwarp();
            for (int a = 0; a < m - 1; a++) {
                int ta = U.sel.clslist[base2 + a];
                if (keepc[ta]) {
                    float4 A = U.sel.obox[ta];
                    for (int b = a + 1 + lane; b < m; b += 32) {
                        int tb = U.sel.clslist[base2 + b];
                        if (keepc[tb] && iou_rn(A, U.sel.obox[tb]) > 0.45f) keepc[tb] = 0;
                    }
                }
                __syncwarp();
            }
            if (which == 0)
                for (int b = lane; b < m; b += 32) {
                    int tb = U.sel.clslist[base2 + b];
                    g_keep[0][img][tb] = keepc[tb];
                }
        }
    }
    __syncthreads();

    // --- Phase E: clean publishes; patch waits + computes loss ---
    if (which == 0) {
        __threadfence();
        if (tid == 0) atomicExch(&g_flag[img], 1);
        return;
    }

    if (tid == 0) { while (atomicAdd(&g_flag[img], 0) == 0) {} }
    __syncthreads();                           // clean data now visible
    if (tid < 80) ccnt[tid] = 0;
    __syncthreads();                           // safe to overlay union

    {   // patch class lists from own smem state
        float4 pb = g_box[1][img][tid];
        U.loss.pdiv[tid] = make_float4(__fdiv_rn(pb.x, 640.0f), __fdiv_rn(pb.y, 640.0f),
                                       __fdiv_rn(pb.z, 640.0f), __fdiv_rn(pb.w, 640.0f));
        if (keepc[tid]) {
            int c = sclz[tid];
            int p = atomicAdd(&ccnt[c], 1);
            if (p < 128) U.loss.plist[c * 128 + p] = (short)tid;
        }
    }
    __syncthreads();

    float ss = 0.0f, nn = 0.0f;
    if (tid < KC && g_keep[0][img][tid]) {
        nn = 1.0f;
        int c = g_cls[0][img][tid];
        float4 cb = g_box[0][img][tid];
        float4 cd = make_float4(__fdiv_rn(cb.x, 640.0f), __fdiv_rn(cb.y, 640.0f),
                                __fdiv_rn(cb.z, 640.0f), __fdiv_rn(cb.w, 640.0f));
        float tm = 0.0f;
        int m = ccnt[c]; if (m > 128) m = 128;
        int base2 = c * 128;
        for (int b2 = 0; b2 < m; b2++)
            tm = fmaxf(tm, iou_rn(cd, U.loss.pdiv[U.loss.plist[base2 + b2]]));
        ss = tm;
    }
    #pragma unroll
    for (int off = 16; off; off >>= 1) {
        ss += __shfl_down_sync(FULL, ss, off);
        nn += __shfl_down_sync(FULL, nn, off);
    }
    if (lane == 0) { rs[w] = ss; rn2[w] = nn; }
    __syncthreads();
    if (tid == 0) {
        float Sm = 0.0f, Nm = 0.0f;
        #pragma unroll
        for (int i = 0; i < 32; i++) { Sm += rs[i]; Nm += rn2[i]; }
        atomicAdd(&g_tot[0], Sm);
        atomicAdd(&g_tot[1], Nm);
        __threadfence();
        int old = atomicAdd(&g_cnt, 1);
        if (old == BIMG - 1) {
            float tot = atomicAdd(&g_tot[0], 0.0f);
            float cnt = atomicAdd(&g_tot[1], 0.0f);
            out[0] = (cnt > 0.0f) ? __fsub_rn(1.0f, __fdiv_rn(tot, fmaxf(cnt, 1.0f)))
                                  : 1.0f;
            g_cnt = 0;
        }
        g_flag[img] = 0;                       // reset for next replay
    }
}

// ---------------- launch ----------------------------------------------------
extern "C" void kernel_launch(void* const* d_in, const int* in_sizes, int n_in,
                              void* d_out, int out_size) {
    const float* clean = (const float*)d_in[0];
    const float* patch = (const float*)d_in[1];

    dim3 sgrid(NTILE, 16);                     // 225 x 16 tiles
    k_score<<<sgrid, 128>>>(clean, patch);
    k_select<<<16, 1024>>>(clean, patch, (float*)d_out);
}